// round 15
// baseline (speedup 1.0000x reference)
#include <cuda_runtime.h>
#include <cuda_bf16.h>
#include <cstdint>
#include <cstddef>

// Problem constants
#define TT   512
#define BSZ  64
#define IC_  512
#define HC_  512
#define ZC_  2048
#define MR   (TT*BSZ)
#define KBIG 1536

#define RK_CTAS 128
#define RK_THR  512
#define NGRP    4
#define GCTAS   32

typedef unsigned long long ull;

// ---------------------------------------------------------------------------
// Static device scratch
// ---------------------------------------------------------------------------
__device__ float g_z[(size_t)MR * ZC_];              // 256 MB
__device__ float g_hseq[(size_t)MR * HC_];           // 64 MB
__device__ __nv_bfloat16 g_hbf[2][NGRP][2][16][HC_]; // h as bf16 hi/lo, [b][k]
__device__ unsigned g_bcnt[NGRP * 32];               // init-rendezvous counters
__device__ unsigned g_bgen[NGRP * 32];
__device__ unsigned g_mono[NGRP * 32];               // monotonic step counters
__device__ __nv_bfloat16 gBbig[(size_t)ZC_ * KBIG];  // 6 MB: [Wh | Wl | Wh], [n][k]

// ---------------------------------------------------------------------------
// Helpers
// ---------------------------------------------------------------------------
__device__ __forceinline__ unsigned atom_add_acqrel(unsigned* p, unsigned v) {
    unsigned old;
    asm volatile("atom.global.add.acq_rel.gpu.u32 %0, [%1], %2;"
                 : "=r"(old) : "l"(p), "r"(v) : "memory");
    return old;
}
__device__ __forceinline__ void red_add_release(unsigned* p, unsigned v) {
    asm volatile("red.global.add.release.gpu.u32 [%0], %1;" :: "l"(p), "r"(v) : "memory");
}
__device__ __forceinline__ unsigned ld_acquire(const unsigned* p) {
    unsigned v;
    asm volatile("ld.global.acquire.gpu.u32 %0, [%1];" : "=r"(v) : "l"(p) : "memory");
    return v;
}
__device__ __forceinline__ void st_release(unsigned* p, unsigned v) {
    asm volatile("st.global.release.gpu.u32 [%0], %1;" :: "l"(p), "r"(v) : "memory");
}
__device__ __forceinline__ float sigf(float x) { return 1.0f / (1.0f + __expf(-x)); }
__device__ __forceinline__ float tanh_fast(float x) {
    float ax = fabsf(x);
    float e = __expf(-2.0f * ax);
    float r = (1.0f - e) / (1.0f + e);
    return copysignf(r, x);
}
__device__ __forceinline__ uint32_t smem_u32(const void* p) {
    uint32_t a;
    asm("{ .reg .u64 t; cvta.to.shared.u64 t, %1; cvt.u32.u64 %0, t; }" : "=r"(a) : "l"(p));
    return a;
}
__device__ __forceinline__ void ldsm_x4(uint32_t* r, uint32_t addr) {
    asm volatile("ldmatrix.sync.aligned.m8n8.x4.shared.b16 {%0,%1,%2,%3}, [%4];"
                 : "=r"(r[0]), "=r"(r[1]), "=r"(r[2]), "=r"(r[3]) : "r"(addr));
}
__device__ __forceinline__ void mma_bf16(float* d, const uint32_t* a, const uint32_t* b) {
    asm volatile(
        "mma.sync.aligned.m16n8k16.row.col.f32.bf16.bf16.f32 "
        "{%0,%1,%2,%3}, {%4,%5,%6,%7}, {%8,%9}, {%0,%1,%2,%3};"
        : "+f"(d[0]), "+f"(d[1]), "+f"(d[2]), "+f"(d[3])
        : "r"(a[0]), "r"(a[1]), "r"(a[2]), "r"(a[3]), "r"(b[0]), "r"(b[1]));
}

// Convert 8 fp32 -> 8 bf16 (hi part, or residual lo part), packed 16B
__device__ __forceinline__ ulonglong2 cvt8(const float4 u, const float4 v, bool lo) {
    const float f[8] = {u.x, u.y, u.z, u.w, v.x, v.y, v.z, v.w};
    __nv_bfloat16 t[8];
#pragma unroll
    for (int q = 0; q < 8; q++) {
        __nv_bfloat16 h = __float2bfloat16(f[q]);
        t[q] = lo ? __float2bfloat16(f[q] - __bfloat162float(h)) : h;
    }
    ulonglong2 r;
    r.x = *(const ull*)t;
    r.y = *(const ull*)(t + 4);
    return r;
}

// ---------------------------------------------------------------------------
// conv_w (R11-exact): W rows 0..511 -> Bbig [2048][1536] = [Wh|Wl|Wh]
// ---------------------------------------------------------------------------
__global__ __launch_bounds__(256) void conv_w(
        const float* __restrict__ W, __nv_bfloat16* __restrict__ Bbig) {
    int idx = blockIdx.x * 256 + threadIdx.x;
    int k = idx >> 11, n = idx & 2047;
    float x = W[idx];
    __nv_bfloat16 h = __float2bfloat16(x);
    __nv_bfloat16 l = __float2bfloat16(x - __bfloat162float(h));
    __nv_bfloat16* row = Bbig + (size_t)n * KBIG;
    row[k]        = h;
    row[512 + k]  = l;
    row[1024 + k] = h;
}

// ---------------------------------------------------------------------------
// Phase 1: fused-conversion HMMA GEMM.
// A read directly as fp32 [MR][512]; logical K=1536 via 3 phases:
//   phase 0,1: stage bf16-hi(A); phase 2: stage bf16-lo(A).
// B = Bbig [2048][1536] bf16 ([Wh|Wl|Wh]). Everything else R11-exact.
// ---------------------------------------------------------------------------
#define ROWB 40
#define AS_BYTES (128 * ROWB * 2)
#define STAGE_BYTES (2 * AS_BYTES)
#define TCSMEM (2 * STAGE_BYTES)

__global__ __launch_bounds__(256, 2) void sgemm_tc(
        const float* __restrict__ A,               // [MR][512] fp32
        const __nv_bfloat16* __restrict__ Bbig,    // [2048][1536]
        const float* __restrict__ bias,            // [2048]
        float* __restrict__ Z) {                   // [MR][2048]
    extern __shared__ char smem[];
    const uint32_t sbase = smem_u32(smem);
    const int tid = threadIdx.x;
    const int wid = tid >> 5, lane = tid & 31;
    const int m0 = blockIdx.y * 128;
    const int n0 = blockIdx.x * 128;
    const int m_warp = (wid & 1) * 64;
    const int n_warp = (wid >> 1) * 32;

    float acc[4][4][4];
#pragma unroll
    for (int i = 0; i < 4; i++)
#pragma unroll
        for (int j = 0; j < 4; j++)
#pragma unroll
            for (int q = 0; q < 4; q++) acc[i][j][q] = 0.f;

    const int c0 = tid * 2;
    const int arow0 = c0 >> 2,       acol0 = (c0 & 3) * 8;
    const int arow1 = (c0 + 1) >> 2, acol1 = ((c0 + 1) & 3) * 8;

    const uint32_t aoff = ((lane & 15) * ROWB + (lane >> 4) * 8) * 2;
    const uint32_t boff = ((((lane >> 4) & 1) * 8 + (lane & 7)) * ROWB
                           + ((lane >> 3) & 1) * 8) * 2;

    const float* aRow0 = A + (size_t)(m0 + arow0) * 512;
    const float* aRow1 = A + (size_t)(m0 + arow1) * 512;

    // Prologue: prefetch it=0 (phase 0 -> kloc 0)
    float4 aPf0a, aPf0b, aPf1a, aPf1b;
    ulonglong2 bPf0, bPf1;
    aPf0a = *(const float4*)(aRow0 + acol0);
    aPf0b = *(const float4*)(aRow0 + acol0 + 4);
    aPf1a = *(const float4*)(aRow1 + acol1);
    aPf1b = *(const float4*)(aRow1 + acol1 + 4);
    bPf0 = *(const ulonglong2*)(Bbig + (size_t)(n0 + arow0) * KBIG + acol0);
    bPf1 = *(const ulonglong2*)(Bbig + (size_t)(n0 + arow1) * KBIG + acol1);

    for (int it = 0; it < KBIG / 32; it++) {
        const int s = it & 1;
        const bool lo = (it >= 32);                 // phase 2 = lo residual
        char* As = smem + s * STAGE_BYTES;
        char* Bs = As + AS_BYTES;

        // Stage (convert A on the fly)
        *(ulonglong2*)(As + arow0 * 80 + acol0 * 2) = cvt8(aPf0a, aPf0b, lo);
        *(ulonglong2*)(As + arow1 * 80 + acol1 * 2) = cvt8(aPf1a, aPf1b, lo);
        *(ulonglong2*)(Bs + arow0 * 80 + acol0 * 2) = bPf0;
        *(ulonglong2*)(Bs + arow1 * 80 + acol1 * 2) = bPf1;
        __syncthreads();

        if (it + 1 < KBIG / 32) {
            const int kbig = (it + 1) * 32;
            const int kloc = kbig & 511;
            aPf0a = *(const float4*)(aRow0 + kloc + acol0);
            aPf0b = *(const float4*)(aRow0 + kloc + acol0 + 4);
            aPf1a = *(const float4*)(aRow1 + kloc + acol1);
            aPf1b = *(const float4*)(aRow1 + kloc + acol1 + 4);
            bPf0 = *(const ulonglong2*)(Bbig + (size_t)(n0 + arow0) * KBIG + kbig + acol0);
            bPf1 = *(const ulonglong2*)(Bbig + (size_t)(n0 + arow1) * KBIG + kbig + acol1);
        }

        const uint32_t sA = sbase + s * STAGE_BYTES;
        const uint32_t sB = sA + AS_BYTES;
#pragma unroll
        for (int ks = 0; ks < 2; ks++) {
            uint32_t af[4][4], bf[2][4];
#pragma unroll
            for (int mi = 0; mi < 4; mi++)
                ldsm_x4(af[mi], sA + (m_warp + 16 * mi) * 80 + ks * 32 + aoff);
#pragma unroll
            for (int j2 = 0; j2 < 2; j2++)
                ldsm_x4(bf[j2], sB + (n_warp + 16 * j2) * 80 + ks * 32 + boff);
#pragma unroll
            for (int mi = 0; mi < 4; mi++)
#pragma unroll
                for (int nj = 0; nj < 4; nj++)
                    mma_bf16(acc[mi][nj], af[mi], &bf[nj >> 1][(nj & 1) * 2]);
        }
        __syncthreads();
    }

#pragma unroll
    for (int mi = 0; mi < 4; mi++) {
        const int r0 = m0 + m_warp + 16 * mi + (lane >> 2);
#pragma unroll
        for (int nj = 0; nj < 4; nj++) {
            const int c = n0 + n_warp + 8 * nj + (lane & 3) * 2;
            float2 bv = *(const float2*)(bias + c);
            float2 o0 = make_float2(acc[mi][nj][0] + bv.x, acc[mi][nj][1] + bv.y);
            float2 o1 = make_float2(acc[mi][nj][2] + bv.x, acc[mi][nj][3] + bv.y);
            *(float2*)(Z + (size_t)r0 * ZC_ + c) = o0;
            *(float2*)(Z + (size_t)(r0 + 8) * ZC_ + c) = o1;
        }
    }
}

// ---------------------------------------------------------------------------
// Phase 2: persistent recurrence (R14-exact)
// ---------------------------------------------------------------------------
#define WROW   2064
#define AROW   1040
#define SM_W   (64 * WROW)
#define SM_AHH SM_W
#define SM_AHL (SM_W + 16640)
#define SM_R   (SM_W + 2 * 16640)
#define RK_SMEM (SM_R + 4 * 64 * 17 * 4)

__global__ __launch_bounds__(RK_THR, 1) void lstm_rec(
        const float* __restrict__ Wh,
        const float* __restrict__ h0l,
        const float* __restrict__ c0l,
        float* __restrict__ hseq,
        float* __restrict__ hs_out,
        float* __restrict__ cs_out) {
    extern __shared__ char smem[];
    const uint32_t sb = smem_u32(smem);
    float* Rsm = (float*)(smem + SM_R);

    const int tid  = threadIdx.x;
    const int cid  = blockIdx.x;
    const int grp  = cid & 3;
    const int cb   = cid >> 2;
    const int wid  = tid >> 5, lane = tid & 31;
    const int ks   = wid >> 2;
    const int nw   = wid & 3;

    unsigned* bcnt = &g_bcnt[grp * 32];
    unsigned* bgen = &g_bgen[grp * 32];
    unsigned* mono = &g_mono[grp * 32];

    unsigned mbase = 0;
    if (tid == 0) mbase = *mono;

    for (int idx = tid; idx < 64 * 512; idx += RK_THR) {
        int c = idx >> 9, k = idx & 511;
        int hcol = c >> 2, gate = c & 3;
        float x = Wh[(size_t)k * ZC_ + (size_t)gate * HC_ + cb * 16 + hcol];
        __nv_bfloat16 h = __float2bfloat16(x);
        __nv_bfloat16 l = __float2bfloat16(x - __bfloat162float(h));
        *(__nv_bfloat16*)(smem + c * WROW + k * 2)        = h;
        *(__nv_bfloat16*)(smem + c * WROW + 1024 + k * 2) = l;
    }

    const uint32_t aoff = ((lane & 15) * 520 + (lane >> 4) * 8) * 2;
    const uint32_t boff = ((((lane >> 4) & 1) * 8 + (lane & 7)) * 1032
                           + ((lane >> 3) & 1) * 8) * 2;
    const uint32_t sBrow = sb + nw * 16 * WROW;

    const int fcol = tid & 15;
    const int fb   = tid >> 4;
    const int hcg  = cb * 16 + fcol;
    const int B    = grp * 16 + fb;
    const float* zbase = g_z + (size_t)B * ZC_ + hcg;
    float cstate = 0.f, hlast = 0.f;
    if (tid < 256) {
        cstate = c0l[hcg];
        hlast  = h0l[hcg];
        __nv_bfloat16 hh = __float2bfloat16(hlast);
        __nv_bfloat16 hl = __float2bfloat16(hlast - __bfloat162float(hh));
        g_hbf[0][grp][0][fb][hcg] = hh;
        g_hbf[0][grp][1][fb][hcg] = hl;
    }
    __syncthreads();
    if (tid == 0) {
        unsigned gen = *bgen;
        unsigned old = atom_add_acqrel(bcnt, 1u);
        if (old == GCTAS - 1) { *bcnt = 0; st_release(bgen, gen + 1); }
        else { while (ld_acquire(bgen) == gen) {} }
    }
    __syncthreads();

    uint32_t bhReg[8][4], blReg[8][4];
#pragma unroll
    for (int k8 = 0; k8 < 8; k8++) {
        ldsm_x4(bhReg[k8], sBrow + (ks * 8 + k8) * 32 + boff);
        ldsm_x4(blReg[k8], sBrow + 1024 + (ks * 8 + k8) * 32 + boff);
    }

    float zc0 = 0.f, zc1 = 0.f, zc2 = 0.f, zc3 = 0.f;
    if (tid < 256) {
        zc0 = __ldcg(zbase);
        zc1 = __ldcg(zbase + HC_);
        zc2 = __ldcg(zbase + 2 * HC_);
        zc3 = __ldcg(zbase + 3 * HC_);
    }

    for (int t = 0; t < TT; t++) {
        {
            const __nv_bfloat16* hsrc = &g_hbf[t & 1][grp][0][0][0];
            ulonglong2 v[4];
            int part[4], row[4], off[4];
#pragma unroll
            for (int j = 0; j < 4; j++) {
                int c = tid + j * 512;
                part[j] = c >> 10;
                int rem = c & 1023;
                row[j] = rem >> 6;
                off[j] = rem & 63;
                v[j] = __ldcg((const ulonglong2*)
                    (hsrc + (size_t)part[j] * 8192 + row[j] * 512 + off[j] * 8));
            }
#pragma unroll
            for (int j = 0; j < 4; j++)
                *(ulonglong2*)(smem + SM_AHH + part[j] * 16640 + row[j] * AROW
                               + off[j] * 16) = v[j];
        }
        __syncthreads();

        float zn0 = 0.f, zn1 = 0.f, zn2 = 0.f, zn3 = 0.f;
        if (tid < 256 && t + 1 < TT) {
            const float* zr = zbase + (size_t)(t + 1) * BSZ * ZC_;
            zn0 = __ldcg(zr);
            zn1 = __ldcg(zr + HC_);
            zn2 = __ldcg(zr + 2 * HC_);
            zn3 = __ldcg(zr + 3 * HC_);
        }

        float acc[2][4];
#pragma unroll
        for (int nt = 0; nt < 2; nt++)
#pragma unroll
            for (int q = 0; q < 4; q++) acc[nt][q] = 0.f;

#pragma unroll
        for (int k8 = 0; k8 < 8; k8++) {
            const int kt = ks * 8 + k8;
            uint32_t ahh[4], ahl[4];
            ldsm_x4(ahh, sb + SM_AHH + kt * 32 + aoff);
            ldsm_x4(ahl, sb + SM_AHL + kt * 32 + aoff);
            mma_bf16(acc[0], ahh, &bhReg[k8][0]);
            mma_bf16(acc[1], ahh, &bhReg[k8][2]);
            mma_bf16(acc[0], ahl, &bhReg[k8][0]);
            mma_bf16(acc[1], ahl, &bhReg[k8][2]);
            mma_bf16(acc[0], ahh, &blReg[k8][0]);
            mma_bf16(acc[1], ahh, &blReg[k8][2]);
        }

#pragma unroll
        for (int nt = 0; nt < 2; nt++) {
            int gc = nw * 16 + nt * 8 + (lane & 3) * 2;
            int b = lane >> 2;
            float* base = Rsm + (ks * 64 + gc) * 17;
            base[b]          = acc[nt][0];
            base[17 + b]     = acc[nt][1];
            base[b + 8]      = acc[nt][2];
            base[17 + b + 8] = acc[nt][3];
        }
        __syncthreads();

        if (tid < 256) {
            float f = zc0, i = zc1, o = zc2, g = zc3;
#pragma unroll
            for (int q = 0; q < 4; q++) {
                const float* r = Rsm + (q * 64 + fcol * 4) * 17 + fb;
                f += r[0];
                i += r[17];
                o += r[34];
                g += r[51];
            }
            f = sigf(f + 1.0f);
            i = sigf(i);
            o = sigf(o);
            g = tanh_fast(g);
            cstate = cstate * f + g * i;
            hlast = o * tanh_fast(cstate);

            __nv_bfloat16 hh = __float2bfloat16(hlast);
            __nv_bfloat16 hl = __float2bfloat16(hlast - __bfloat162float(hh));
            g_hbf[(t + 1) & 1][grp][0][fb][hcg] = hh;
            g_hbf[(t + 1) & 1][grp][1][fb][hcg] = hl;
        }
        zc0 = zn0; zc1 = zn1; zc2 = zn2; zc3 = zn3;

        __syncthreads();
        if (tid == 0) red_add_release(mono, 1u);
        if (tid < 256)
            hseq[(size_t)(t * BSZ + B) * HC_ + hcg] = hlast;
        if (tid == 0) {
            const unsigned tgt = mbase + (unsigned)GCTAS * (unsigned)(t + 1);
            while ((int)(ld_acquire(mono) - tgt) < 0) {}
        }
        __syncthreads();
    }

    if (tid < 256) {
        hs_out[B * HC_ + hcg] = hlast;
        cs_out[B * HC_ + hcg] = cstate;
    }
}

// ---------------------------------------------------------------------------
// Launch
// ---------------------------------------------------------------------------
extern "C" void kernel_launch(void* const* d_in, const int* in_sizes, int n_in,
                              void* d_out, int out_size) {
    const float* x  = (const float*)d_in[0];
    const float* W0 = (const float*)d_in[1];
    const float* b0 = (const float*)d_in[2];
    const float* W1 = (const float*)d_in[3];
    const float* b1 = (const float*)d_in[4];
    const float* h0 = (const float*)d_in[5];
    const float* c0 = (const float*)d_in[6];

    float* out = (float*)d_out;
    float* hs  = out + (size_t)TT * BSZ * HC_;
    float* cs  = hs + (size_t)2 * BSZ * HC_;

    float *zptr = nullptr, *hseq0 = nullptr;
    __nv_bfloat16 *bbig = nullptr;
    cudaGetSymbolAddress((void**)&zptr, g_z);
    cudaGetSymbolAddress((void**)&hseq0, g_hseq);
    cudaGetSymbolAddress((void**)&bbig, gBbig);

    static int attr_set = 0;
    if (!attr_set) {
        cudaFuncSetAttribute(lstm_rec, cudaFuncAttributeMaxDynamicSharedMemorySize, RK_SMEM);
        cudaFuncSetAttribute(sgemm_tc, cudaFuncAttributeMaxDynamicSharedMemorySize, TCSMEM);
        attr_set = 1;
    }

    dim3 tgrid(ZC_ / 128, MR / 128);

    // Layer 0
    conv_w<<<(512 * ZC_) / 256, 256>>>(W0, bbig);
    sgemm_tc<<<tgrid, 256, TCSMEM>>>(x, bbig, b0, zptr);
    lstm_rec<<<RK_CTAS, RK_THR, RK_SMEM>>>(W0 + (size_t)IC_ * ZC_, h0, c0,
                                           hseq0, hs, cs);
    // Layer 1
    conv_w<<<(512 * ZC_) / 256, 256>>>(W1, bbig);
    sgemm_tc<<<tgrid, 256, TCSMEM>>>(hseq0, bbig, b1, zptr);
    lstm_rec<<<RK_CTAS, RK_THR, RK_SMEM>>>(W1 + (size_t)HC_ * ZC_, h0 + HC_, c0 + HC_,
                                           out, hs + BSZ * HC_, cs + BSZ * HC_);
}

// round 16
// speedup vs baseline: 1.0509x; 1.0509x over previous
#include <cuda_runtime.h>
#include <cuda_bf16.h>
#include <cstdint>
#include <cstddef>

// Problem constants
#define TT   512
#define BSZ  64
#define IC_  512
#define HC_  512
#define ZC_  2048
#define MR   (TT*BSZ)
#define KBIG 1536

#define RK_CTAS 128
#define RK_THR  512
#define NGRP    4
#define GCTAS   32

typedef unsigned long long ull;

// ---------------------------------------------------------------------------
// Static device scratch
// ---------------------------------------------------------------------------
__device__ float g_z[(size_t)MR * ZC_];              // 256 MB
__device__ __nv_bfloat16 g_hbf[2][NGRP][2][16][HC_]; // h as bf16 hi/lo, [b][k]
__device__ unsigned g_bcnt[NGRP * 32];               // init-rendezvous counters
__device__ unsigned g_bgen[NGRP * 32];
__device__ unsigned g_mono[NGRP * 32];               // monotonic step counters
__device__ __nv_bfloat16 gAbig[(size_t)MR * KBIG];   // 96 MB: [Ah | Ah | Al]
__device__ __nv_bfloat16 gBbig[(size_t)ZC_ * KBIG];  // 6 MB:  [Wh | Wl | Wh]

// ---------------------------------------------------------------------------
// Helpers
// ---------------------------------------------------------------------------
__device__ __forceinline__ unsigned atom_add_acqrel(unsigned* p, unsigned v) {
    unsigned old;
    asm volatile("atom.global.add.acq_rel.gpu.u32 %0, [%1], %2;"
                 : "=r"(old) : "l"(p), "r"(v) : "memory");
    return old;
}
__device__ __forceinline__ void red_add_release(unsigned* p, unsigned v) {
    asm volatile("red.global.add.release.gpu.u32 [%0], %1;" :: "l"(p), "r"(v) : "memory");
}
__device__ __forceinline__ unsigned ld_acquire(const unsigned* p) {
    unsigned v;
    asm volatile("ld.global.acquire.gpu.u32 %0, [%1];" : "=r"(v) : "l"(p) : "memory");
    return v;
}
__device__ __forceinline__ void st_release(unsigned* p, unsigned v) {
    asm volatile("st.global.release.gpu.u32 [%0], %1;" :: "l"(p), "r"(v) : "memory");
}
__device__ __forceinline__ float sigf(float x) { return 1.0f / (1.0f + __expf(-x)); }
__device__ __forceinline__ float tanh_fast(float x) {
    float ax = fabsf(x);
    float e = __expf(-2.0f * ax);
    float r = (1.0f - e) / (1.0f + e);
    return copysignf(r, x);
}
__device__ __forceinline__ uint32_t smem_u32(const void* p) {
    uint32_t a;
    asm("{ .reg .u64 t; cvta.to.shared.u64 t, %1; cvt.u32.u64 %0, t; }" : "=r"(a) : "l"(p));
    return a;
}
__device__ __forceinline__ void ldsm_x4(uint32_t* r, uint32_t addr) {
    asm volatile("ldmatrix.sync.aligned.m8n8.x4.shared.b16 {%0,%1,%2,%3}, [%4];"
                 : "=r"(r[0]), "=r"(r[1]), "=r"(r[2]), "=r"(r[3]) : "r"(addr));
}
__device__ __forceinline__ void mma_bf16(float* d, const uint32_t* a, const uint32_t* b) {
    asm volatile(
        "mma.sync.aligned.m16n8k16.row.col.f32.bf16.bf16.f32 "
        "{%0,%1,%2,%3}, {%4,%5,%6,%7}, {%8,%9}, {%0,%1,%2,%3};"
        : "+f"(d[0]), "+f"(d[1]), "+f"(d[2]), "+f"(d[3])
        : "r"(a[0]), "r"(a[1]), "r"(a[2]), "r"(a[3]), "r"(b[0]), "r"(b[1]));
}

// ---------------------------------------------------------------------------
// Conversion kernels (R11-exact)
// ---------------------------------------------------------------------------
__global__ __launch_bounds__(256) void conv_a(
        const float* __restrict__ A, __nv_bfloat16* __restrict__ Abig) {
    size_t i = ((size_t)blockIdx.x * 256 + threadIdx.x) * 4;
    int m = (int)(i >> 9), k = (int)(i & 511);
    float4 v = *(const float4*)(A + i);
    __nv_bfloat16 h[4], l[4];
    const float* vf = (const float*)&v;
#pragma unroll
    for (int q = 0; q < 4; q++) {
        h[q] = __float2bfloat16(vf[q]);
        l[q] = __float2bfloat16(vf[q] - __bfloat162float(h[q]));
    }
    __nv_bfloat16* row = Abig + (size_t)m * KBIG;
    *(ull*)(row + k)        = *(const ull*)h;
    *(ull*)(row + 512 + k)  = *(const ull*)h;
    *(ull*)(row + 1024 + k) = *(const ull*)l;
}

__global__ __launch_bounds__(256) void conv_w(
        const float* __restrict__ W, __nv_bfloat16* __restrict__ Bbig) {
    int idx = blockIdx.x * 256 + threadIdx.x;
    int k = idx >> 11, n = idx & 2047;
    float x = W[idx];
    __nv_bfloat16 h = __float2bfloat16(x);
    __nv_bfloat16 l = __float2bfloat16(x - __bfloat162float(h));
    __nv_bfloat16* row = Bbig + (size_t)n * KBIG;
    row[k]        = h;
    row[512 + k]  = l;
    row[1024 + k] = h;
}

// ---------------------------------------------------------------------------
// Phase 1: HMMA GEMM (R14-exact: bf16 Abig path)
// ---------------------------------------------------------------------------
#define ROWB 40
#define AS_BYTES (128 * ROWB * 2)
#define STAGE_BYTES (2 * AS_BYTES)
#define TCSMEM (2 * STAGE_BYTES)

__global__ __launch_bounds__(256, 2) void sgemm_tc(
        const __nv_bfloat16* __restrict__ Abig,
        const __nv_bfloat16* __restrict__ Bbig,
        const float* __restrict__ bias,
        float* __restrict__ Z) {
    extern __shared__ char smem[];
    const uint32_t sbase = smem_u32(smem);
    const int tid = threadIdx.x;
    const int wid = tid >> 5, lane = tid & 31;
    const int m0 = blockIdx.y * 128;
    const int n0 = blockIdx.x * 128;
    const int m_warp = (wid & 1) * 64;
    const int n_warp = (wid >> 1) * 32;

    float acc[4][4][4];
#pragma unroll
    for (int i = 0; i < 4; i++)
#pragma unroll
        for (int j = 0; j < 4; j++)
#pragma unroll
            for (int q = 0; q < 4; q++) acc[i][j][q] = 0.f;

    const int c0 = tid * 2;
    const int arow0 = c0 >> 2,       acol0 = (c0 & 3) * 8;
    const int arow1 = (c0 + 1) >> 2, acol1 = ((c0 + 1) & 3) * 8;

    const uint32_t aoff = ((lane & 15) * ROWB + (lane >> 4) * 8) * 2;
    const uint32_t boff = ((((lane >> 4) & 1) * 8 + (lane & 7)) * ROWB
                           + ((lane >> 3) & 1) * 8) * 2;

    ulonglong2 aPf0, aPf1, bPf0, bPf1;
    aPf0 = *(const ulonglong2*)(Abig + (size_t)(m0 + arow0) * KBIG + acol0);
    aPf1 = *(const ulonglong2*)(Abig + (size_t)(m0 + arow1) * KBIG + acol1);
    bPf0 = *(const ulonglong2*)(Bbig + (size_t)(n0 + arow0) * KBIG + acol0);
    bPf1 = *(const ulonglong2*)(Bbig + (size_t)(n0 + arow1) * KBIG + acol1);

    for (int it = 0; it < KBIG / 32; it++) {
        const int s = it & 1;
        char* As = smem + s * STAGE_BYTES;
        char* Bs = As + AS_BYTES;

        *(ulonglong2*)(As + arow0 * 80 + acol0 * 2) = aPf0;
        *(ulonglong2*)(As + arow1 * 80 + acol1 * 2) = aPf1;
        *(ulonglong2*)(Bs + arow0 * 80 + acol0 * 2) = bPf0;
        *(ulonglong2*)(Bs + arow1 * 80 + acol1 * 2) = bPf1;
        __syncthreads();

        if (it + 1 < KBIG / 32) {
            const int kb = (it + 1) * 32;
            aPf0 = *(const ulonglong2*)(Abig + (size_t)(m0 + arow0) * KBIG + kb + acol0);
            aPf1 = *(const ulonglong2*)(Abig + (size_t)(m0 + arow1) * KBIG + kb + acol1);
            bPf0 = *(const ulonglong2*)(Bbig + (size_t)(n0 + arow0) * KBIG + kb + acol0);
            bPf1 = *(const ulonglong2*)(Bbig + (size_t)(n0 + arow1) * KBIG + kb + acol1);
        }

        const uint32_t sA = sbase + s * STAGE_BYTES;
        const uint32_t sB = sA + AS_BYTES;
#pragma unroll
        for (int ks = 0; ks < 2; ks++) {
            uint32_t af[4][4], bf[2][4];
#pragma unroll
            for (int mi = 0; mi < 4; mi++)
                ldsm_x4(af[mi], sA + (m_warp + 16 * mi) * 80 + ks * 32 + aoff);
#pragma unroll
            for (int j2 = 0; j2 < 2; j2++)
                ldsm_x4(bf[j2], sB + (n_warp + 16 * j2) * 80 + ks * 32 + boff);
#pragma unroll
            for (int mi = 0; mi < 4; mi++)
#pragma unroll
                for (int nj = 0; nj < 4; nj++)
                    mma_bf16(acc[mi][nj], af[mi], &bf[nj >> 1][(nj & 1) * 2]);
        }
        __syncthreads();
    }

#pragma unroll
    for (int mi = 0; mi < 4; mi++) {
        const int r0 = m0 + m_warp + 16 * mi + (lane >> 2);
#pragma unroll
        for (int nj = 0; nj < 4; nj++) {
            const int c = n0 + n_warp + 8 * nj + (lane & 3) * 2;
            float2 bv = *(const float2*)(bias + c);
            float2 o0 = make_float2(acc[mi][nj][0] + bv.x, acc[mi][nj][1] + bv.y);
            float2 o1 = make_float2(acc[mi][nj][2] + bv.x, acc[mi][nj][3] + bv.y);
            *(float2*)(Z + (size_t)r0 * ZC_ + c) = o0;
            *(float2*)(Z + (size_t)(r0 + 8) * ZC_ + c) = o1;
        }
    }
}

// ---------------------------------------------------------------------------
// Phase 2: persistent recurrence (R14-exact) with dual output mode:
//  - abig_out != 0: write h directly as bf16 [Ah|Ah|Al] rows of gAbig (L0)
//  - hseq_out != 0: write fp32 h sequence (L1 -> final out)
// Both writes happen in the barrier-wait window.
// ---------------------------------------------------------------------------
#define WROW   2064
#define AROW   1040
#define SM_W   (64 * WROW)
#define SM_AHH SM_W
#define SM_AHL (SM_W + 16640)
#define SM_R   (SM_W + 2 * 16640)
#define RK_SMEM (SM_R + 4 * 64 * 17 * 4)

__global__ __launch_bounds__(RK_THR, 1) void lstm_rec(
        const float* __restrict__ Wh,
        const float* __restrict__ h0l,
        const float* __restrict__ c0l,
        float* __restrict__ hseq_out,            // may be null
        __nv_bfloat16* __restrict__ abig_out,    // may be null
        float* __restrict__ hs_out,
        float* __restrict__ cs_out) {
    extern __shared__ char smem[];
    const uint32_t sb = smem_u32(smem);
    float* Rsm = (float*)(smem + SM_R);

    const int tid  = threadIdx.x;
    const int cid  = blockIdx.x;
    const int grp  = cid & 3;
    const int cb   = cid >> 2;
    const int wid  = tid >> 5, lane = tid & 31;
    const int ks   = wid >> 2;
    const int nw   = wid & 3;

    unsigned* bcnt = &g_bcnt[grp * 32];
    unsigned* bgen = &g_bgen[grp * 32];
    unsigned* mono = &g_mono[grp * 32];

    unsigned mbase = 0;
    if (tid == 0) mbase = *mono;

    for (int idx = tid; idx < 64 * 512; idx += RK_THR) {
        int c = idx >> 9, k = idx & 511;
        int hcol = c >> 2, gate = c & 3;
        float x = Wh[(size_t)k * ZC_ + (size_t)gate * HC_ + cb * 16 + hcol];
        __nv_bfloat16 h = __float2bfloat16(x);
        __nv_bfloat16 l = __float2bfloat16(x - __bfloat162float(h));
        *(__nv_bfloat16*)(smem + c * WROW + k * 2)        = h;
        *(__nv_bfloat16*)(smem + c * WROW + 1024 + k * 2) = l;
    }

    const uint32_t aoff = ((lane & 15) * 520 + (lane >> 4) * 8) * 2;
    const uint32_t boff = ((((lane >> 4) & 1) * 8 + (lane & 7)) * 1032
                           + ((lane >> 3) & 1) * 8) * 2;
    const uint32_t sBrow = sb + nw * 16 * WROW;

    const int fcol = tid & 15;
    const int fb   = tid >> 4;
    const int hcg  = cb * 16 + fcol;
    const int B    = grp * 16 + fb;
    const float* zbase = g_z + (size_t)B * ZC_ + hcg;
    float cstate = 0.f, hlast = 0.f;
    if (tid < 256) {
        cstate = c0l[hcg];
        hlast  = h0l[hcg];
        __nv_bfloat16 hh = __float2bfloat16(hlast);
        __nv_bfloat16 hl = __float2bfloat16(hlast - __bfloat162float(hh));
        g_hbf[0][grp][0][fb][hcg] = hh;
        g_hbf[0][grp][1][fb][hcg] = hl;
    }
    __syncthreads();
    if (tid == 0) {
        unsigned gen = *bgen;
        unsigned old = atom_add_acqrel(bcnt, 1u);
        if (old == GCTAS - 1) { *bcnt = 0; st_release(bgen, gen + 1); }
        else { while (ld_acquire(bgen) == gen) {} }
    }
    __syncthreads();

    uint32_t bhReg[8][4], blReg[8][4];
#pragma unroll
    for (int k8 = 0; k8 < 8; k8++) {
        ldsm_x4(bhReg[k8], sBrow + (ks * 8 + k8) * 32 + boff);
        ldsm_x4(blReg[k8], sBrow + 1024 + (ks * 8 + k8) * 32 + boff);
    }

    float zc0 = 0.f, zc1 = 0.f, zc2 = 0.f, zc3 = 0.f;
    if (tid < 256) {
        zc0 = __ldcg(zbase);
        zc1 = __ldcg(zbase + HC_);
        zc2 = __ldcg(zbase + 2 * HC_);
        zc3 = __ldcg(zbase + 3 * HC_);
    }

    for (int t = 0; t < TT; t++) {
        {
            const __nv_bfloat16* hsrc = &g_hbf[t & 1][grp][0][0][0];
            ulonglong2 v[4];
            int part[4], row[4], off[4];
#pragma unroll
            for (int j = 0; j < 4; j++) {
                int c = tid + j * 512;
                part[j] = c >> 10;
                int rem = c & 1023;
                row[j] = rem >> 6;
                off[j] = rem & 63;
                v[j] = __ldcg((const ulonglong2*)
                    (hsrc + (size_t)part[j] * 8192 + row[j] * 512 + off[j] * 8));
            }
#pragma unroll
            for (int j = 0; j < 4; j++)
                *(ulonglong2*)(smem + SM_AHH + part[j] * 16640 + row[j] * AROW
                               + off[j] * 16) = v[j];
        }
        __syncthreads();

        float zn0 = 0.f, zn1 = 0.f, zn2 = 0.f, zn3 = 0.f;
        if (tid < 256 && t + 1 < TT) {
            const float* zr = zbase + (size_t)(t + 1) * BSZ * ZC_;
            zn0 = __ldcg(zr);
            zn1 = __ldcg(zr + HC_);
            zn2 = __ldcg(zr + 2 * HC_);
            zn3 = __ldcg(zr + 3 * HC_);
        }

        float acc[2][4];
#pragma unroll
        for (int nt = 0; nt < 2; nt++)
#pragma unroll
            for (int q = 0; q < 4; q++) acc[nt][q] = 0.f;

#pragma unroll
        for (int k8 = 0; k8 < 8; k8++) {
            const int kt = ks * 8 + k8;
            uint32_t ahh[4], ahl[4];
            ldsm_x4(ahh, sb + SM_AHH + kt * 32 + aoff);
            ldsm_x4(ahl, sb + SM_AHL + kt * 32 + aoff);
            mma_bf16(acc[0], ahh, &bhReg[k8][0]);
            mma_bf16(acc[1], ahh, &bhReg[k8][2]);
            mma_bf16(acc[0], ahl, &bhReg[k8][0]);
            mma_bf16(acc[1], ahl, &bhReg[k8][2]);
            mma_bf16(acc[0], ahh, &blReg[k8][0]);
            mma_bf16(acc[1], ahh, &blReg[k8][2]);
        }

#pragma unroll
        for (int nt = 0; nt < 2; nt++) {
            int gc = nw * 16 + nt * 8 + (lane & 3) * 2;
            int b = lane >> 2;
            float* base = Rsm + (ks * 64 + gc) * 17;
            base[b]          = acc[nt][0];
            base[17 + b]     = acc[nt][1];
            base[b + 8]      = acc[nt][2];
            base[17 + b + 8] = acc[nt][3];
        }
        __syncthreads();

        __nv_bfloat16 hh, hl;
        if (tid < 256) {
            float f = zc0, i = zc1, o = zc2, g = zc3;
#pragma unroll
            for (int q = 0; q < 4; q++) {
                const float* r = Rsm + (q * 64 + fcol * 4) * 17 + fb;
                f += r[0];
                i += r[17];
                o += r[34];
                g += r[51];
            }
            f = sigf(f + 1.0f);
            i = sigf(i);
            o = sigf(o);
            g = tanh_fast(g);
            cstate = cstate * f + g * i;
            hlast = o * tanh_fast(cstate);

            hh = __float2bfloat16(hlast);
            hl = __float2bfloat16(hlast - __bfloat162float(hh));
            g_hbf[(t + 1) & 1][grp][0][fb][hcg] = hh;
            g_hbf[(t + 1) & 1][grp][1][fb][hcg] = hl;
        }
        zc0 = zn0; zc1 = zn1; zc2 = zn2; zc3 = zn3;

        // Barrier: arrive, fold the sequence-output stores into the wait window
        __syncthreads();
        if (tid == 0) red_add_release(mono, 1u);
        if (tid < 256) {
            const size_t m = (size_t)(t * BSZ + B);
            if (abig_out) {
                __nv_bfloat16* row = abig_out + m * KBIG + hcg;
                row[0]    = hh;
                row[512]  = hh;
                row[1024] = hl;
            }
            if (hseq_out)
                hseq_out[m * HC_ + hcg] = hlast;
        }
        if (tid == 0) {
            const unsigned tgt = mbase + (unsigned)GCTAS * (unsigned)(t + 1);
            while ((int)(ld_acquire(mono) - tgt) < 0) {}
        }
        __syncthreads();
    }

    if (tid < 256) {
        hs_out[B * HC_ + hcg] = hlast;
        cs_out[B * HC_ + hcg] = cstate;
    }
}

// ---------------------------------------------------------------------------
// Launch: conv_w+conv_a+sgemm+rec(L0 -> Abig bf16), conv_w+sgemm+rec(L1 -> out)
// ---------------------------------------------------------------------------
extern "C" void kernel_launch(void* const* d_in, const int* in_sizes, int n_in,
                              void* d_out, int out_size) {
    const float* x  = (const float*)d_in[0];
    const float* W0 = (const float*)d_in[1];
    const float* b0 = (const float*)d_in[2];
    const float* W1 = (const float*)d_in[3];
    const float* b1 = (const float*)d_in[4];
    const float* h0 = (const float*)d_in[5];
    const float* c0 = (const float*)d_in[6];

    float* out = (float*)d_out;
    float* hs  = out + (size_t)TT * BSZ * HC_;
    float* cs  = hs + (size_t)2 * BSZ * HC_;

    float* zptr = nullptr;
    __nv_bfloat16 *abig = nullptr, *bbig = nullptr;
    cudaGetSymbolAddress((void**)&zptr, g_z);
    cudaGetSymbolAddress((void**)&abig, gAbig);
    cudaGetSymbolAddress((void**)&bbig, gBbig);

    static int attr_set = 0;
    if (!attr_set) {
        cudaFuncSetAttribute(lstm_rec, cudaFuncAttributeMaxDynamicSharedMemorySize, RK_SMEM);
        cudaFuncSetAttribute(sgemm_tc, cudaFuncAttributeMaxDynamicSharedMemorySize, TCSMEM);
        attr_set = 1;
    }

    dim3 tgrid(ZC_ / 128, MR / 128);

    // Layer 0: project x, recur, emit h directly as bf16 Abig for layer 1
    conv_w<<<(512 * ZC_) / 256, 256>>>(W0, bbig);
    conv_a<<<(MR * IC_) / 1024, 256>>>(x, abig);
    sgemm_tc<<<tgrid, 256, TCSMEM>>>(abig, bbig, b0, zptr);
    lstm_rec<<<RK_CTAS, RK_THR, RK_SMEM>>>(W0 + (size_t)IC_ * ZC_, h0, c0,
                                           nullptr, abig, hs, cs);
    // Layer 1: project L0's h (already in Abig), recur, emit fp32 out
    conv_w<<<(512 * ZC_) / 256, 256>>>(W1, bbig);
    sgemm_tc<<<tgrid, 256, TCSMEM>>>(abig, bbig, b1, zptr);
    lstm_rec<<<RK_CTAS, RK_THR, RK_SMEM>>>(W1 + (size_t)HC_ * ZC_, h0 + HC_, c0 + HC_,
                                           out, nullptr, hs + BSZ * HC_, cs + BSZ * HC_);
}

// round 17
// speedup vs baseline: 1.0792x; 1.0269x over previous
#include <cuda_runtime.h>
#include <cuda_bf16.h>
#include <cstdint>
#include <cstddef>

// Problem constants
#define TT   512
#define BSZ  64
#define IC_  512
#define HC_  512
#define ZC_  2048
#define MR   (TT*BSZ)
#define KBIG 1536

#define RK_CTAS 128
#define RK_THR  512
#define NGRP    4
#define GCTAS   32

typedef unsigned long long ull;

// ---------------------------------------------------------------------------
// Static device scratch
// ---------------------------------------------------------------------------
__device__ float g_z[(size_t)MR * ZC_];              // 256 MB
__device__ __nv_bfloat16 g_hbf[2][NGRP][2][16][HC_]; // h as bf16 hi/lo, [b][k]
__device__ unsigned g_bcnt[NGRP * 32];               // init-rendezvous counters
__device__ unsigned g_bgen[NGRP * 32];
__device__ unsigned g_mono[NGRP * 32];               // monotonic step counters
__device__ __nv_bfloat16 gAbig[(size_t)MR * KBIG];   // 96 MB: [Ah | Ah | Al]
__device__ __nv_bfloat16 gBbig[2][(size_t)ZC_ * KBIG]; // 2 x 6 MB: [Wh|Wl|Wh]

// ---------------------------------------------------------------------------
// Helpers
// ---------------------------------------------------------------------------
__device__ __forceinline__ unsigned atom_add_acqrel(unsigned* p, unsigned v) {
    unsigned old;
    asm volatile("atom.global.add.acq_rel.gpu.u32 %0, [%1], %2;"
                 : "=r"(old) : "l"(p), "r"(v) : "memory");
    return old;
}
__device__ __forceinline__ void red_add_release(unsigned* p, unsigned v) {
    asm volatile("red.global.add.release.gpu.u32 [%0], %1;" :: "l"(p), "r"(v) : "memory");
}
__device__ __forceinline__ unsigned ld_acquire(const unsigned* p) {
    unsigned v;
    asm volatile("ld.global.acquire.gpu.u32 %0, [%1];" : "=r"(v) : "l"(p) : "memory");
    return v;
}
__device__ __forceinline__ void st_release(unsigned* p, unsigned v) {
    asm volatile("st.global.release.gpu.u32 [%0], %1;" :: "l"(p), "r"(v) : "memory");
}
__device__ __forceinline__ float sigf(float x) { return 1.0f / (1.0f + __expf(-x)); }
__device__ __forceinline__ float tanh_fast(float x) {
    float ax = fabsf(x);
    float e = __expf(-2.0f * ax);
    float r = (1.0f - e) / (1.0f + e);
    return copysignf(r, x);
}
__device__ __forceinline__ uint32_t smem_u32(const void* p) {
    uint32_t a;
    asm("{ .reg .u64 t; cvta.to.shared.u64 t, %1; cvt.u32.u64 %0, t; }" : "=r"(a) : "l"(p));
    return a;
}
__device__ __forceinline__ void ldsm_x4(uint32_t* r, uint32_t addr) {
    asm volatile("ldmatrix.sync.aligned.m8n8.x4.shared.b16 {%0,%1,%2,%3}, [%4];"
                 : "=r"(r[0]), "=r"(r[1]), "=r"(r[2]), "=r"(r[3]) : "r"(addr));
}
__device__ __forceinline__ void mma_bf16(float* d, const uint32_t* a, const uint32_t* b) {
    asm volatile(
        "mma.sync.aligned.m16n8k16.row.col.f32.bf16.bf16.f32 "
        "{%0,%1,%2,%3}, {%4,%5,%6,%7}, {%8,%9}, {%0,%1,%2,%3};"
        : "+f"(d[0]), "+f"(d[1]), "+f"(d[2]), "+f"(d[3])
        : "r"(a[0]), "r"(a[1]), "r"(a[2]), "r"(a[3]), "r"(b[0]), "r"(b[1]));
}

// ---------------------------------------------------------------------------
// Conversion kernels (R11-exact)
// ---------------------------------------------------------------------------
__global__ __launch_bounds__(256) void conv_a(
        const float* __restrict__ A, __nv_bfloat16* __restrict__ Abig) {
    size_t i = ((size_t)blockIdx.x * 256 + threadIdx.x) * 4;
    int m = (int)(i >> 9), k = (int)(i & 511);
    float4 v = *(const float4*)(A + i);
    __nv_bfloat16 h[4], l[4];
    const float* vf = (const float*)&v;
#pragma unroll
    for (int q = 0; q < 4; q++) {
        h[q] = __float2bfloat16(vf[q]);
        l[q] = __float2bfloat16(vf[q] - __bfloat162float(h[q]));
    }
    __nv_bfloat16* row = Abig + (size_t)m * KBIG;
    *(ull*)(row + k)        = *(const ull*)h;
    *(ull*)(row + 512 + k)  = *(const ull*)h;
    *(ull*)(row + 1024 + k) = *(const ull*)l;
}

__global__ __launch_bounds__(256) void conv_w(
        const float* __restrict__ W, __nv_bfloat16* __restrict__ Bbig) {
    int idx = blockIdx.x * 256 + threadIdx.x;
    int k = idx >> 11, n = idx & 2047;
    float x = W[idx];
    __nv_bfloat16 h = __float2bfloat16(x);
    __nv_bfloat16 l = __float2bfloat16(x - __bfloat162float(h));
    __nv_bfloat16* row = Bbig + (size_t)n * KBIG;
    row[k]        = h;
    row[512 + k]  = l;
    row[1024 + k] = h;
}

// ---------------------------------------------------------------------------
// Phase 1: HMMA GEMM, tile M=256 x N=128 (B traffic halved vs 128x128).
// 512 threads, 16 warps: warp tile 64m x 32n (R11-identical per-warp geometry).
// smem: A 256x(32k) + B 128x(32k) per stage (80B rows), double-buffered = 60KB.
// ---------------------------------------------------------------------------
#define ROWB 40
#define A_STG (256 * 80)               // 20480 B
#define B_STG (128 * 80)               // 10240 B
#define STAGE_BYTES (A_STG + B_STG)    // 30720 B
#define TCSMEM (2 * STAGE_BYTES)       // 61440 B

__global__ __launch_bounds__(512, 1) void sgemm_tc(
        const __nv_bfloat16* __restrict__ Abig,    // [MR][1536]
        const __nv_bfloat16* __restrict__ Bbig,    // [2048][1536]
        const float* __restrict__ bias,            // [2048]
        float* __restrict__ Z) {                   // [MR][2048]
    extern __shared__ char smem[];
    const uint32_t sbase = smem_u32(smem);
    const int tid = threadIdx.x;
    const int wid = tid >> 5, lane = tid & 31;
    const int m0 = blockIdx.y * 256;
    const int n0 = blockIdx.x * 128;
    const int m_warp = (wid & 3) * 64;
    const int n_warp = (wid >> 2) * 32;

    float acc[4][4][4];
#pragma unroll
    for (int i = 0; i < 4; i++)
#pragma unroll
        for (int j = 0; j < 4; j++)
#pragma unroll
            for (int q = 0; q < 4; q++) acc[i][j][q] = 0.f;

    // Staging maps: A = 1024 16B-chunks (2/thread), B = 512 chunks (1/thread)
    const int c0 = tid * 2;
    const int arow0 = c0 >> 2,       acol0 = (c0 & 3) * 8;
    const int arow1 = (c0 + 1) >> 2, acol1 = ((c0 + 1) & 3) * 8;
    const int brow = tid >> 2,       bcol = (tid & 3) * 8;

    // ldmatrix per-lane byte offsets (R11-verified)
    const uint32_t aoff = ((lane & 15) * ROWB + (lane >> 4) * 8) * 2;
    const uint32_t boff = ((((lane >> 4) & 1) * 8 + (lane & 7)) * ROWB
                           + ((lane >> 3) & 1) * 8) * 2;

    ulonglong2 aPf0, aPf1, bPf;
    aPf0 = *(const ulonglong2*)(Abig + (size_t)(m0 + arow0) * KBIG + acol0);
    aPf1 = *(const ulonglong2*)(Abig + (size_t)(m0 + arow1) * KBIG + acol1);
    bPf  = *(const ulonglong2*)(Bbig + (size_t)(n0 + brow) * KBIG + bcol);

    for (int it = 0; it < KBIG / 32; it++) {
        const int s = it & 1;
        char* As = smem + s * STAGE_BYTES;
        char* Bs = As + A_STG;

        *(ulonglong2*)(As + arow0 * 80 + acol0 * 2) = aPf0;
        *(ulonglong2*)(As + arow1 * 80 + acol1 * 2) = aPf1;
        *(ulonglong2*)(Bs + brow * 80 + bcol * 2)   = bPf;
        __syncthreads();

        if (it + 1 < KBIG / 32) {
            const int kb = (it + 1) * 32;
            aPf0 = *(const ulonglong2*)(Abig + (size_t)(m0 + arow0) * KBIG + kb + acol0);
            aPf1 = *(const ulonglong2*)(Abig + (size_t)(m0 + arow1) * KBIG + kb + acol1);
            bPf  = *(const ulonglong2*)(Bbig + (size_t)(n0 + brow) * KBIG + kb + bcol);
        }

        const uint32_t sA = sbase + s * STAGE_BYTES;
        const uint32_t sB = sA + A_STG;
#pragma unroll
        for (int ks = 0; ks < 2; ks++) {
            uint32_t af[4][4], bf[2][4];
#pragma unroll
            for (int mi = 0; mi < 4; mi++)
                ldsm_x4(af[mi], sA + (m_warp + 16 * mi) * 80 + ks * 32 + aoff);
#pragma unroll
            for (int j2 = 0; j2 < 2; j2++)
                ldsm_x4(bf[j2], sB + (n_warp + 16 * j2) * 80 + ks * 32 + boff);
#pragma unroll
            for (int mi = 0; mi < 4; mi++)
#pragma unroll
                for (int nj = 0; nj < 4; nj++)
                    mma_bf16(acc[mi][nj], af[mi], &bf[nj >> 1][(nj & 1) * 2]);
        }
        __syncthreads();
    }

#pragma unroll
    for (int mi = 0; mi < 4; mi++) {
        const int r0 = m0 + m_warp + 16 * mi + (lane >> 2);
#pragma unroll
        for (int nj = 0; nj < 4; nj++) {
            const int c = n0 + n_warp + 8 * nj + (lane & 3) * 2;
            float2 bv = *(const float2*)(bias + c);
            float2 o0 = make_float2(acc[mi][nj][0] + bv.x, acc[mi][nj][1] + bv.y);
            float2 o1 = make_float2(acc[mi][nj][2] + bv.x, acc[mi][nj][3] + bv.y);
            *(float2*)(Z + (size_t)r0 * ZC_ + c) = o0;
            *(float2*)(Z + (size_t)(r0 + 8) * ZC_ + c) = o1;
        }
    }
}

// ---------------------------------------------------------------------------
// Phase 2: persistent recurrence (R16-exact, dual output mode)
// ---------------------------------------------------------------------------
#define WROW   2064
#define AROW   1040
#define SM_W   (64 * WROW)
#define SM_AHH SM_W
#define SM_AHL (SM_W + 16640)
#define SM_R   (SM_W + 2 * 16640)
#define RK_SMEM (SM_R + 4 * 64 * 17 * 4)

__global__ __launch_bounds__(RK_THR, 1) void lstm_rec(
        const float* __restrict__ Wh,
        const float* __restrict__ h0l,
        const float* __restrict__ c0l,
        float* __restrict__ hseq_out,            // may be null
        __nv_bfloat16* __restrict__ abig_out,    // may be null
        float* __restrict__ hs_out,
        float* __restrict__ cs_out) {
    extern __shared__ char smem[];
    const uint32_t sb = smem_u32(smem);
    float* Rsm = (float*)(smem + SM_R);

    const int tid  = threadIdx.x;
    const int cid  = blockIdx.x;
    const int grp  = cid & 3;
    const int cb   = cid >> 2;
    const int wid  = tid >> 5, lane = tid & 31;
    const int ks   = wid >> 2;
    const int nw   = wid & 3;

    unsigned* bcnt = &g_bcnt[grp * 32];
    unsigned* bgen = &g_bgen[grp * 32];
    unsigned* mono = &g_mono[grp * 32];

    unsigned mbase = 0;
    if (tid == 0) mbase = *mono;

    for (int idx = tid; idx < 64 * 512; idx += RK_THR) {
        int c = idx >> 9, k = idx & 511;
        int hcol = c >> 2, gate = c & 3;
        float x = Wh[(size_t)k * ZC_ + (size_t)gate * HC_ + cb * 16 + hcol];
        __nv_bfloat16 h = __float2bfloat16(x);
        __nv_bfloat16 l = __float2bfloat16(x - __bfloat162float(h));
        *(__nv_bfloat16*)(smem + c * WROW + k * 2)        = h;
        *(__nv_bfloat16*)(smem + c * WROW + 1024 + k * 2) = l;
    }

    const uint32_t aoff = ((lane & 15) * 520 + (lane >> 4) * 8) * 2;
    const uint32_t boff = ((((lane >> 4) & 1) * 8 + (lane & 7)) * 1032
                           + ((lane >> 3) & 1) * 8) * 2;
    const uint32_t sBrow = sb + nw * 16 * WROW;

    const int fcol = tid & 15;
    const int fb   = tid >> 4;
    const int hcg  = cb * 16 + fcol;
    const int B    = grp * 16 + fb;
    const float* zbase = g_z + (size_t)B * ZC_ + hcg;
    float cstate = 0.f, hlast = 0.f;
    if (tid < 256) {
        cstate = c0l[hcg];
        hlast  = h0l[hcg];
        __nv_bfloat16 hh = __float2bfloat16(hlast);
        __nv_bfloat16 hl = __float2bfloat16(hlast - __bfloat162float(hh));
        g_hbf[0][grp][0][fb][hcg] = hh;
        g_hbf[0][grp][1][fb][hcg] = hl;
    }
    __syncthreads();
    if (tid == 0) {
        unsigned gen = *bgen;
        unsigned old = atom_add_acqrel(bcnt, 1u);
        if (old == GCTAS - 1) { *bcnt = 0; st_release(bgen, gen + 1); }
        else { while (ld_acquire(bgen) == gen) {} }
    }
    __syncthreads();

    uint32_t bhReg[8][4], blReg[8][4];
#pragma unroll
    for (int k8 = 0; k8 < 8; k8++) {
        ldsm_x4(bhReg[k8], sBrow + (ks * 8 + k8) * 32 + boff);
        ldsm_x4(blReg[k8], sBrow + 1024 + (ks * 8 + k8) * 32 + boff);
    }

    float zc0 = 0.f, zc1 = 0.f, zc2 = 0.f, zc3 = 0.f;
    if (tid < 256) {
        zc0 = __ldcg(zbase);
        zc1 = __ldcg(zbase + HC_);
        zc2 = __ldcg(zbase + 2 * HC_);
        zc3 = __ldcg(zbase + 3 * HC_);
    }

    for (int t = 0; t < TT; t++) {
        {
            const __nv_bfloat16* hsrc = &g_hbf[t & 1][grp][0][0][0];
            ulonglong2 v[4];
            int part[4], row[4], off[4];
#pragma unroll
            for (int j = 0; j < 4; j++) {
                int c = tid + j * 512;
                part[j] = c >> 10;
                int rem = c & 1023;
                row[j] = rem >> 6;
                off[j] = rem & 63;
                v[j] = __ldcg((const ulonglong2*)
                    (hsrc + (size_t)part[j] * 8192 + row[j] * 512 + off[j] * 8));
            }
#pragma unroll
            for (int j = 0; j < 4; j++)
                *(ulonglong2*)(smem + SM_AHH + part[j] * 16640 + row[j] * AROW
                               + off[j] * 16) = v[j];
        }
        __syncthreads();

        float zn0 = 0.f, zn1 = 0.f, zn2 = 0.f, zn3 = 0.f;
        if (tid < 256 && t + 1 < TT) {
            const float* zr = zbase + (size_t)(t + 1) * BSZ * ZC_;
            zn0 = __ldcg(zr);
            zn1 = __ldcg(zr + HC_);
            zn2 = __ldcg(zr + 2 * HC_);
            zn3 = __ldcg(zr + 3 * HC_);
        }

        float acc[2][4];
#pragma unroll
        for (int nt = 0; nt < 2; nt++)
#pragma unroll
            for (int q = 0; q < 4; q++) acc[nt][q] = 0.f;

#pragma unroll
        for (int k8 = 0; k8 < 8; k8++) {
            const int kt = ks * 8 + k8;
            uint32_t ahh[4], ahl[4];
            ldsm_x4(ahh, sb + SM_AHH + kt * 32 + aoff);
            ldsm_x4(ahl, sb + SM_AHL + kt * 32 + aoff);
            mma_bf16(acc[0], ahh, &bhReg[k8][0]);
            mma_bf16(acc[1], ahh, &bhReg[k8][2]);
            mma_bf16(acc[0], ahl, &bhReg[k8][0]);
            mma_bf16(acc[1], ahl, &bhReg[k8][2]);
            mma_bf16(acc[0], ahh, &blReg[k8][0]);
            mma_bf16(acc[1], ahh, &blReg[k8][2]);
        }

#pragma unroll
        for (int nt = 0; nt < 2; nt++) {
            int gc = nw * 16 + nt * 8 + (lane & 3) * 2;
            int b = lane >> 2;
            float* base = Rsm + (ks * 64 + gc) * 17;
            base[b]          = acc[nt][0];
            base[17 + b]     = acc[nt][1];
            base[b + 8]      = acc[nt][2];
            base[17 + b + 8] = acc[nt][3];
        }
        __syncthreads();

        __nv_bfloat16 hh, hl;
        if (tid < 256) {
            float f = zc0, i = zc1, o = zc2, g = zc3;
#pragma unroll
            for (int q = 0; q < 4; q++) {
                const float* r = Rsm + (q * 64 + fcol * 4) * 17 + fb;
                f += r[0];
                i += r[17];
                o += r[34];
                g += r[51];
            }
            f = sigf(f + 1.0f);
            i = sigf(i);
            o = sigf(o);
            g = tanh_fast(g);
            cstate = cstate * f + g * i;
            hlast = o * tanh_fast(cstate);

            hh = __float2bfloat16(hlast);
            hl = __float2bfloat16(hlast - __bfloat162float(hh));
            g_hbf[(t + 1) & 1][grp][0][fb][hcg] = hh;
            g_hbf[(t + 1) & 1][grp][1][fb][hcg] = hl;
        }
        zc0 = zn0; zc1 = zn1; zc2 = zn2; zc3 = zn3;

        __syncthreads();
        if (tid == 0) red_add_release(mono, 1u);
        if (tid < 256) {
            const size_t m = (size_t)(t * BSZ + B);
            if (abig_out) {
                __nv_bfloat16* row = abig_out + m * KBIG + hcg;
                row[0]    = hh;
                row[512]  = hh;
                row[1024] = hl;
            }
            if (hseq_out)
                hseq_out[m * HC_ + hcg] = hlast;
        }
        if (tid == 0) {
            const unsigned tgt = mbase + (unsigned)GCTAS * (unsigned)(t + 1);
            while ((int)(ld_acquire(mono) - tgt) < 0) {}
        }
        __syncthreads();
    }

    if (tid < 256) {
        hs_out[B * HC_ + hcg] = hlast;
        cs_out[B * HC_ + hcg] = cstate;
    }
}

// ---------------------------------------------------------------------------
// Launch: conv_w(L0,L1 upfront) + conv_a -> sgemm L0 -> rec L0(->Abig) ->
//         sgemm L1 -> rec L1(->out)
// ---------------------------------------------------------------------------
extern "C" void kernel_launch(void* const* d_in, const int* in_sizes, int n_in,
                              void* d_out, int out_size) {
    const float* x  = (const float*)d_in[0];
    const float* W0 = (const float*)d_in[1];
    const float* b0 = (const float*)d_in[2];
    const float* W1 = (const float*)d_in[3];
    const float* b1 = (const float*)d_in[4];
    const float* h0 = (const float*)d_in[5];
    const float* c0 = (const float*)d_in[6];

    float* out = (float*)d_out;
    float* hs  = out + (size_t)TT * BSZ * HC_;
    float* cs  = hs + (size_t)2 * BSZ * HC_;

    float* zptr = nullptr;
    __nv_bfloat16 *abig = nullptr, *bbig = nullptr;
    cudaGetSymbolAddress((void**)&zptr, g_z);
    cudaGetSymbolAddress((void**)&abig, gAbig);
    cudaGetSymbolAddress((void**)&bbig, gBbig);
    __nv_bfloat16* bbig1 = bbig + (size_t)ZC_ * KBIG;

    static int attr_set = 0;
    if (!attr_set) {
        cudaFuncSetAttribute(lstm_rec, cudaFuncAttributeMaxDynamicSharedMemorySize, RK_SMEM);
        cudaFuncSetAttribute(sgemm_tc, cudaFuncAttributeMaxDynamicSharedMemorySize, TCSMEM);
        attr_set = 1;
    }

    dim3 tgrid(ZC_ / 128, MR / 256);

    // Upfront conversions (both layers' weights + layer-0 activations)
    conv_w<<<(512 * ZC_) / 256, 256>>>(W0, bbig);
    conv_w<<<(512 * ZC_) / 256, 256>>>(W1, bbig1);
    conv_a<<<(MR * IC_) / 1024, 256>>>(x, abig);

    // Layer 0
    sgemm_tc<<<tgrid, 512, TCSMEM>>>(abig, bbig, b0, zptr);
    lstm_rec<<<RK_CTAS, RK_THR, RK_SMEM>>>(W0 + (size_t)IC_ * ZC_, h0, c0,
                                           nullptr, abig, hs, cs);
    // Layer 1
    sgemm_tc<<<tgrid, 512, TCSMEM>>>(abig, bbig1, b1, zptr);
    lstm_rec<<<RK_CTAS, RK_THR, RK_SMEM>>>(W1 + (size_t)HC_ * ZC_, h0 + HC_, c0 + HC_,
                                           out, nullptr, hs + BSZ * HC_, cs + BSZ * HC_);
}